// round 5
// baseline (speedup 1.0000x reference)
#include <cuda_runtime.h>

#define BB 256
#define RR 1152
#define CC 10
#define OO 16
#define II 8
#define CO 160            // CC*OO
#define KK (RR*II)        // 9216
#define NITER 3
#define KSPLIT 144        // k_spart: K chunks of 64 k (8 r)

typedef unsigned long long ull;

__device__ float g_xT[KK*BB];            // x transposed [k][b] (for k_spart)
__device__ float g_b[CC*RR];             // logits [c][r]
__device__ float g_c[CC*RR];             // couplings [c][r]
__device__ float g_part[KSPLIT*BB*CO];   // split-K partials of S (23.6 MB)
__device__ float g_V[BB*CO];             // squashed v [b][co]

// ---------------- f32x2 helpers --------------------------------------------
__device__ __forceinline__ ull ffma2(ull a, ull b, ull c) {
    ull d;
    asm("fma.rn.f32x2 %0, %1, %2, %3;" : "=l"(d) : "l"(a), "l"(b), "l"(c));
    return d;
}
__device__ __forceinline__ float squashf(float s) {
    return s * fabsf(s) / (1.0f + s*s);
}

// ---------------------------------------------------------------------------
// prep: transpose x[b][k] -> xT[k][b] + init logits/couplings
// ---------------------------------------------------------------------------
__global__ void __launch_bounds__(256) k_prep(const float* __restrict__ x) {
    __shared__ float tile[64][66];
    int t = threadIdx.x;
    int k0 = blockIdx.x * 64, b0 = blockIdx.y * 64;

    #pragma unroll
    for (int j = 0; j < 4; j++) {
        int idx = t + j*256;
        int bb = idx >> 4, c4 = idx & 15;
        float4 v = *(const float4*)(x + (size_t)(b0+bb)*KK + k0 + c4*4);
        tile[c4*4+0][bb] = v.x; tile[c4*4+1][bb] = v.y;
        tile[c4*4+2][bb] = v.z; tile[c4*4+3][bb] = v.w;
    }
    __syncthreads();
    #pragma unroll
    for (int j = 0; j < 4; j++) {
        int idx = t + j*256;
        int kk = idx >> 4, b4 = idx & 15;
        float4 v;
        v.x = tile[kk][b4*4+0]; v.y = tile[kk][b4*4+1];
        v.z = tile[kk][b4*4+2]; v.w = tile[kk][b4*4+3];
        *(float4*)(g_xT + (size_t)(k0+kk)*BB + b0 + b4*4) = v;
    }
    int id = (blockIdx.y * 144 + blockIdx.x) * 256 + t;
    if (id < CC*RR) { g_b[id] = 0.0f; g_c[id] = 1.0f / (float)RR; }
}

// ---------------------------------------------------------------------------
// s GEMM partials: part[ks][b][co] = sum_{k in 64-chunk} (cW)[k,co]*xT[k,b]
// grid (144, 2), 256 thr, 2 CTAs/SM. Block tile 128b x 160co, 8 stages of 8k.
// x pre-SPLATTED in smem: per k-step 40 FFMA2 : 9 LDS : 0 MOV.
// ---------------------------------------------------------------------------
__global__ void __launch_bounds__(256, 2) k_spart(const float* __restrict__ W) {
    __shared__ __align__(16) float sX2[2][8][256];   // x splatted [k][2b]
    __shared__ __align__(16) float sW[2][8][160];
    __shared__ float sc[80];

    int t = threadIdx.x;
    int w = t >> 5, l = t & 31;
    int wb = w >> 2, wc = w & 3;
    int lb = l >> 2, lc = l & 3;
    int ks = blockIdx.x, bt = blockIdx.y;
    int r0 = ks * 8;
    int b0 = bt * 128;
    int xb0 = wb*64 + lb*8;          // first of 8 b
    int wc0 = wc*40 + lc*10;         // first of 10 co

    if (t < 80) sc[t] = g_c[(t % 10)*RR + r0 + (t / 10)];

    int kl = t >> 5, b4 = t & 31;    // staging roles
    float4 rx, rwa, rwb;
    float  rs = 0.0f;

    __syncthreads();

    // prologue: load + commit stage 0
    rx = *(const float4*)(g_xT + (size_t)(r0*8 + kl)*BB + b0 + b4*4);
    if (t < 160) {
        const float* wp = W + ((size_t)r0*CO + t)*II;
        rwa = *(const float4*)(wp);
        rwb = *(const float4*)(wp + 4);
        rs  = sc[t >> 4];
    }
    *(float4*)&sX2[0][kl][b4*8]     = make_float4(rx.x, rx.x, rx.y, rx.y);
    *(float4*)&sX2[0][kl][b4*8 + 4] = make_float4(rx.z, rx.z, rx.w, rx.w);
    if (t < 160) {
        sW[0][0][t] = rwa.x*rs; sW[0][1][t] = rwa.y*rs;
        sW[0][2][t] = rwa.z*rs; sW[0][3][t] = rwa.w*rs;
        sW[0][4][t] = rwb.x*rs; sW[0][5][t] = rwb.y*rs;
        sW[0][6][t] = rwb.z*rs; sW[0][7][t] = rwb.w*rs;
    }

    ull acc[8][5];
    #pragma unroll
    for (int bi = 0; bi < 8; bi++)
        #pragma unroll
        for (int j = 0; j < 5; j++) acc[bi][j] = 0ull;

    for (int s = 0; s < 8; s++) {
        int p = s & 1;
        if (s < 7) {
            int r = r0 + s + 1;
            rx = *(const float4*)(g_xT + (size_t)(r*8 + kl)*BB + b0 + b4*4);
            if (t < 160) {
                const float* wp = W + ((size_t)r*CO + t)*II;
                rwa = *(const float4*)(wp);
                rwb = *(const float4*)(wp + 4);
                rs  = sc[(s+1)*10 + (t >> 4)];
            }
        }
        __syncthreads();

        #pragma unroll
        for (int kk = 0; kk < 8; kk++) {
            ulonglong2 xa = *(const ulonglong2*)&sX2[p][kk][2*xb0];
            ulonglong2 xb_ = *(const ulonglong2*)&sX2[p][kk][2*xb0 + 4];
            ulonglong2 xc = *(const ulonglong2*)&sX2[p][kk][2*xb0 + 8];
            ulonglong2 xd = *(const ulonglong2*)&sX2[p][kk][2*xb0 + 12];
            ull xs[8] = {xa.x, xa.y, xb_.x, xb_.y, xc.x, xc.y, xd.x, xd.y};
            ull wv[5];
            const float* wrow = &sW[p][kk][wc0];
            #pragma unroll
            for (int j = 0; j < 5; j++) wv[j] = *(const ull*)(wrow + 2*j);
            #pragma unroll
            for (int bi = 0; bi < 8; bi++)
                #pragma unroll
                for (int j = 0; j < 5; j++)
                    acc[bi][j] = ffma2(wv[j], xs[bi], acc[bi][j]);
        }

        if (s < 7) {
            int q = (s + 1) & 1;
            *(float4*)&sX2[q][kl][b4*8]     = make_float4(rx.x, rx.x, rx.y, rx.y);
            *(float4*)&sX2[q][kl][b4*8 + 4] = make_float4(rx.z, rx.z, rx.w, rx.w);
            if (t < 160) {
                sW[q][0][t] = rwa.x*rs; sW[q][1][t] = rwa.y*rs;
                sW[q][2][t] = rwa.z*rs; sW[q][3][t] = rwa.w*rs;
                sW[q][4][t] = rwb.x*rs; sW[q][5][t] = rwb.y*rs;
                sW[q][6][t] = rwb.z*rs; sW[q][7][t] = rwb.w*rs;
            }
        }
    }

    float* dst = g_part + (size_t)ks*BB*CO;
    #pragma unroll
    for (int bi = 0; bi < 8; bi++) {
        float* row = dst + (size_t)(b0 + xb0 + bi)*CO + wc0;
        #pragma unroll
        for (int j = 0; j < 5; j++) *(ull*)(row + 2*j) = acc[bi][j];
    }
}

// ---------------------------------------------------------------------------
// reduce split-K partials, squash -> g_V (+ final output)
// grid 160 x 256: 64 f4 per block, 4-way p-split + smem tree
// ---------------------------------------------------------------------------
__global__ void __launch_bounds__(256) k_sqreduce(float* __restrict__ out,
                                                  int write_out) {
    __shared__ float4 red[256];
    int t = threadIdx.x;
    int i4 = t & 63, pg = t >> 6;
    int idx4 = blockIdx.x * 64 + i4;
    float4 s = make_float4(0,0,0,0);
    #pragma unroll 6
    for (int p = pg*36; p < (pg+1)*36; p++) {
        float4 v = *(const float4*)(g_part + (size_t)p*BB*CO + (size_t)idx4*4);
        s.x += v.x; s.y += v.y; s.z += v.z; s.w += v.w;
    }
    red[t] = s;
    __syncthreads();
    if (t < 64) {
        float4 a = red[t], b = red[t+64], c = red[t+128], d = red[t+192];
        s.x = (a.x + b.x) + (c.x + d.x);
        s.y = (a.y + b.y) + (c.y + d.y);
        s.z = (a.z + b.z) + (c.z + d.z);
        s.w = (a.w + b.w) + (c.w + d.w);
        float4 q;
        q.x = squashf(s.x); q.y = squashf(s.y);
        q.z = squashf(s.z); q.w = squashf(s.w);
        *(float4*)(g_V + (size_t)idx4*4) = q;
        if (write_out) *(float4*)(out + (size_t)idx4*4) = q;
    }
}

// ---------------------------------------------------------------------------
// agree: partial G[k,co] = sum_{b half} x[b,k]*V[b,co]; contract with W,
// atomicAdd into logits. grid (144, 2), 2 CTAs/SM.
// x staged straight from input (f4), pre-splatted. 20 FFMA2 : 7 LDS per b.
// ---------------------------------------------------------------------------
__global__ void __launch_bounds__(256, 2) k_agree(const float* __restrict__ x,
                                                  const float* __restrict__ W) {
    __shared__ __align__(16) float sm[64*162];   // 41.5 KB (reused as sG)
    float* sV   = sm;           // [32][160] = 5120
    float* sXa2 = sm + 5120;    // [32][136] splatted k = 4352

    int t = threadIdx.x;
    int w = t >> 5, l = t & 31;
    int wk = w >> 2, wc = w & 3;
    int lk = l >> 2, lc = l & 3;
    int r0 = blockIdx.x * 8;
    int k0 = r0 * 8;
    int klq = wk*32 + lk*4;
    int wc0 = wc*40 + lc*10;

    ull acc[4][5];
    #pragma unroll
    for (int ki = 0; ki < 4; ki++)
        #pragma unroll
        for (int j = 0; j < 5; j++) acc[ki][j] = 0ull;

    for (int sub = 0; sub < 4; sub++) {
        int bs0 = blockIdx.y * 128 + sub * 32;
        __syncthreads();
        // stage V: 1280 f4 coalesced
        #pragma unroll
        for (int q = 0; q < 5; q++) {
            int idx = t + q*256;
            *(float4*)&sV[idx*4] =
                *(const float4*)(g_V + (size_t)bs0*CO + (size_t)idx*4);
        }
        // stage x direct from input, pre-splatted: 512 f4 loads
        #pragma unroll
        for (int q = 0; q < 2; q++) {
            int idx = t + q*256;
            int bb = idx >> 4, c4 = idx & 15;
            float4 v = *(const float4*)(x + (size_t)(bs0+bb)*KK + k0 + c4*4);
            *(float4*)&sXa2[bb*136 + c4*8]     = make_float4(v.x, v.x, v.y, v.y);
            *(float4*)&sXa2[bb*136 + c4*8 + 4] = make_float4(v.z, v.z, v.w, v.w);
        }
        __syncthreads();

        #pragma unroll 2
        for (int b = 0; b < 32; b++) {
            ulonglong2 xa = *(const ulonglong2*)&sXa2[b*136 + 2*klq];
            ulonglong2 xb_ = *(const ulonglong2*)&sXa2[b*136 + 2*klq + 4];
            ull xs[4] = {xa.x, xa.y, xb_.x, xb_.y};
            ull vv[5];
            const float* vrow = &sV[b*160 + wc0];
            #pragma unroll
            for (int j = 0; j < 5; j++) vv[j] = *(const ull*)(vrow + 2*j);
            #pragma unroll
            for (int ki = 0; ki < 4; ki++)
                #pragma unroll
                for (int j = 0; j < 5; j++)
                    acc[ki][j] = ffma2(vv[j], xs[ki], acc[ki][j]);
        }
    }
    __syncthreads();

    // spill partial G: sG[k][co], stride 162
    #pragma unroll
    for (int ki = 0; ki < 4; ki++)
        #pragma unroll
        for (int j = 0; j < 5; j++)
            *(ull*)&sm[(klq + ki)*162 + wc0 + 2*j] = acc[ki][j];
    __syncthreads();

    // contraction: warp w -> route r0+w
    int r = r0 + w;
    const float* G = &sm[(w*8)*162];
    for (int c = 0; c < CC; c++) {
        float4 w4 = *(const float4*)(W + ((size_t)r*CC + c)*OO*II + 4*l);
        int e0 = 4*l;
        float p = w4.x * G[((e0  )&7)*162 + c*16 + ((e0  )>>3)]
                + w4.y * G[((e0+1)&7)*162 + c*16 + ((e0+1)>>3)]
                + w4.z * G[((e0+2)&7)*162 + c*16 + ((e0+2)>>3)]
                + w4.w * G[((e0+3)&7)*162 + c*16 + ((e0+3)>>3)];
        #pragma unroll
        for (int off = 16; off; off >>= 1)
            p += __shfl_xor_sync(0xffffffffu, p, off);
        if (l == 0) atomicAdd(&g_b[c*RR + r], p * (1.0f / (float)BB));
    }
}

// ---------------------------------------------------------------------------
// softmax over routes per class ([c][r] layout)
// ---------------------------------------------------------------------------
__global__ void __launch_bounds__(256) k_softmax() {
    int c = blockIdx.x, t = threadIdx.x;
    __shared__ float red[8];

    float v[5];
    #pragma unroll
    for (int q = 0; q < 5; q++) {
        int r = t + q*256;
        v[q] = (r < RR) ? g_b[c*RR + r] : -1e30f;
    }
    float m = fmaxf(fmaxf(fmaxf(v[0], v[1]), fmaxf(v[2], v[3])), v[4]);
    #pragma unroll
    for (int off = 16; off; off >>= 1) m = fmaxf(m, __shfl_xor_sync(~0u, m, off));
    if ((t & 31) == 0) red[t >> 5] = m;
    __syncthreads();
    m = red[0];
    #pragma unroll
    for (int q = 1; q < 8; q++) m = fmaxf(m, red[q]);

    float e[5], sum = 0.0f;
    #pragma unroll
    for (int q = 0; q < 5; q++) {
        int r = t + q*256;
        e[q] = (r < RR) ? __expf(v[q] - m) : 0.0f;
        sum += e[q];
    }
    #pragma unroll
    for (int off = 16; off; off >>= 1) sum += __shfl_xor_sync(~0u, sum, off);
    __syncthreads();
    if ((t & 31) == 0) red[t >> 5] = sum;
    __syncthreads();
    sum = 0.0f;
    #pragma unroll
    for (int q = 0; q < 8; q++) sum += red[q];
    float inv = 1.0f / sum;

    #pragma unroll
    for (int q = 0; q < 5; q++) {
        int r = t + q*256;
        if (r < RR) g_c[c*RR + r] = e[q] * inv;
    }
}

// ---------------------------------------------------------------------------
extern "C" void kernel_launch(void* const* d_in, const int* in_sizes, int n_in,
                              void* d_out, int out_size) {
    const float* x = (const float*)d_in[0];
    const float* W = (const float*)d_in[1];
    if (in_sizes[0] == RR*CC*OO*II && in_sizes[1] == BB*RR*II) {
        W = (const float*)d_in[0];
        x = (const float*)d_in[1];
    }
    float* out = (float*)d_out;

    k_prep<<<dim3(144, 4), 256>>>(x);
    for (int it = 0; it < NITER; it++) {
        k_spart<<<dim3(KSPLIT, 2), 256>>>(W);
        k_sqreduce<<<160, 256>>>(out, it == NITER - 1 ? 1 : 0);
        if (it < NITER - 1) {
            k_agree<<<dim3(144, 2), 256>>>(x, W);
            k_softmax<<<CC, 256>>>();
        }
    }
}

// round 6
// speedup vs baseline: 1.0057x; 1.0057x over previous
#include <cuda_runtime.h>

#define BB 256
#define RR 1152
#define CC 10
#define OO 16
#define II 8
#define CO 160            // CC*OO
#define KK (RR*II)        // 9216
#define NITER 3
#define KSPLIT 144        // k_spart: K chunks of 64 k (8 r)

typedef unsigned long long ull;

__device__ float g_xT[KK*BB];            // x transposed [k][b] (for k_spart)
__device__ float g_b[CC*RR];             // logits [c][r]
__device__ float g_c[CC*RR];             // couplings [c][r]
__device__ float g_part[KSPLIT*BB*CO];   // split-K partials of S
__device__ float g_V2[BB*CO*2];          // squashed v, SPLATTED [b][2*co]

// ---------------- f32x2 helpers --------------------------------------------
__device__ __forceinline__ ull ffma2(ull a, ull b, ull c) {
    ull d;
    asm("fma.rn.f32x2 %0, %1, %2, %3;" : "=l"(d) : "l"(a), "l"(b), "l"(c));
    return d;
}
__device__ __forceinline__ void unpack2(ull a, float* lo, float* hi) {
    unsigned l_, h_;
    asm("mov.b64 {%0, %1}, %2;" : "=r"(l_), "=r"(h_) : "l"(a));
    *lo = __uint_as_float(l_); *hi = __uint_as_float(h_);
}
__device__ __forceinline__ float squashf(float s) {
    return s * fabsf(s) / (1.0f + s*s);
}

// ---------------------------------------------------------------------------
// prep: transpose x[b][k] -> xT[k][b] + init logits/couplings
// ---------------------------------------------------------------------------
__global__ void __launch_bounds__(256) k_prep(const float* __restrict__ x) {
    __shared__ float tile[64][66];
    int t = threadIdx.x;
    int k0 = blockIdx.x * 64, b0 = blockIdx.y * 64;

    #pragma unroll
    for (int j = 0; j < 4; j++) {
        int idx = t + j*256;
        int bb = idx >> 4, c4 = idx & 15;
        float4 v = *(const float4*)(x + (size_t)(b0+bb)*KK + k0 + c4*4);
        tile[c4*4+0][bb] = v.x; tile[c4*4+1][bb] = v.y;
        tile[c4*4+2][bb] = v.z; tile[c4*4+3][bb] = v.w;
    }
    __syncthreads();
    #pragma unroll
    for (int j = 0; j < 4; j++) {
        int idx = t + j*256;
        int kk = idx >> 4, b4 = idx & 15;
        float4 v;
        v.x = tile[kk][b4*4+0]; v.y = tile[kk][b4*4+1];
        v.z = tile[kk][b4*4+2]; v.w = tile[kk][b4*4+3];
        *(float4*)(g_xT + (size_t)(k0+kk)*BB + b0 + b4*4) = v;
    }
    int id = (blockIdx.y * 144 + blockIdx.x) * 256 + t;
    if (id < CC*RR) { g_b[id] = 0.0f; g_c[id] = 1.0f / (float)RR; }
}

// ---------------------------------------------------------------------------
// s GEMM partials: part[ks][b][co] = sum_{k in 64-chunk} (cW)[k,co]*xT[k,b]
// grid (144, 2), 2 CTAs/SM. Block tile 128b x 160co, 8 stages of 8 k.
// f32x2 pairs over b (natural from xT); W SPLATTED at staging.
// Inner loop per k: 2 LDS.128(x) + 5 LDS.128(Wsplat) + 40 FFMA2, 0 MOV.
// ---------------------------------------------------------------------------
__global__ void __launch_bounds__(256, 2) k_spart(const float* __restrict__ W) {
    __shared__ __align__(16) float sX[2][8][128];    // x, natural b-major
    __shared__ __align__(16) float sWs[2][8][320];   // W scaled+splatted
    __shared__ float sc[80];

    int t = threadIdx.x;
    int w = t >> 5, l = t & 31;
    int wb = w >> 2, wc = w & 3;
    int lb = l >> 2, lc = l & 3;
    int ks = blockIdx.x, bt = blockIdx.y;
    int r0 = ks * 8;
    int b0 = bt * 128;
    int xb0 = wb*64 + lb*8;          // 8 b = 4 natural pairs
    int wc0 = wc*40 + lc*10;         // 10 co

    if (t < 80) sc[t] = g_c[(t % 10)*RR + r0 + (t / 10)];

    int kl = t >> 5, b4 = t & 31;    // staging roles
    float4 rx, rwa, rwb;
    float  rs = 0.0f;

    __syncthreads();

    // prologue: load + commit stage 0
    rx = *(const float4*)(g_xT + (size_t)(r0*8 + kl)*BB + b0 + b4*4);
    if (t < 160) {
        const float* wp = W + ((size_t)r0*CO + t)*II;
        rwa = *(const float4*)(wp);
        rwb = *(const float4*)(wp + 4);
        rs  = sc[t >> 4];
    }
    *(float4*)&sX[0][kl][b4*4] = rx;
    if (t < 160) {
        float2* c0 = (float2*)&sWs[0][0][2*t];
        float v0 = rwa.x*rs; c0[0*160] = make_float2(v0, v0);
        float v1 = rwa.y*rs; c0[1*160] = make_float2(v1, v1);
        float v2 = rwa.z*rs; c0[2*160] = make_float2(v2, v2);
        float v3 = rwa.w*rs; c0[3*160] = make_float2(v3, v3);
        float v4 = rwb.x*rs; c0[4*160] = make_float2(v4, v4);
        float v5 = rwb.y*rs; c0[5*160] = make_float2(v5, v5);
        float v6 = rwb.z*rs; c0[6*160] = make_float2(v6, v6);
        float v7 = rwb.w*rs; c0[7*160] = make_float2(v7, v7);
    }

    ull acc[4][10];
    #pragma unroll
    for (int bp = 0; bp < 4; bp++)
        #pragma unroll
        for (int j = 0; j < 10; j++) acc[bp][j] = 0ull;

    for (int s = 0; s < 8; s++) {
        int p = s & 1;
        if (s < 7) {
            int r = r0 + s + 1;
            rx = *(const float4*)(g_xT + (size_t)(r*8 + kl)*BB + b0 + b4*4);
            if (t < 160) {
                const float* wp = W + ((size_t)r*CO + t)*II;
                rwa = *(const float4*)(wp);
                rwb = *(const float4*)(wp + 4);
                rs  = sc[(s+1)*10 + (t >> 4)];
            }
        }
        __syncthreads();

        #pragma unroll
        for (int kk = 0; kk < 8; kk++) {
            ulonglong2 xa = *(const ulonglong2*)&sX[p][kk][xb0];
            ulonglong2 xb_ = *(const ulonglong2*)&sX[p][kk][xb0 + 4];
            ull xp[4] = {xa.x, xa.y, xb_.x, xb_.y};
            ull wv[10];
            const float* wrow = &sWs[p][kk][2*wc0];
            #pragma unroll
            for (int u = 0; u < 5; u++) {
                ulonglong2 wq = *(const ulonglong2*)(wrow + 4*u);
                wv[2*u] = wq.x; wv[2*u+1] = wq.y;
            }
            #pragma unroll
            for (int bp = 0; bp < 4; bp++)
                #pragma unroll
                for (int j = 0; j < 10; j++)
                    acc[bp][j] = ffma2(xp[bp], wv[j], acc[bp][j]);
        }

        if (s < 7) {
            int q = (s + 1) & 1;
            *(float4*)&sX[q][kl][b4*4] = rx;
            if (t < 160) {
                float2* c0 = (float2*)&sWs[q][0][2*t];
                float v0 = rwa.x*rs; c0[0*160] = make_float2(v0, v0);
                float v1 = rwa.y*rs; c0[1*160] = make_float2(v1, v1);
                float v2 = rwa.z*rs; c0[2*160] = make_float2(v2, v2);
                float v3 = rwa.w*rs; c0[3*160] = make_float2(v3, v3);
                float v4 = rwb.x*rs; c0[4*160] = make_float2(v4, v4);
                float v5 = rwb.y*rs; c0[5*160] = make_float2(v5, v5);
                float v6 = rwb.z*rs; c0[6*160] = make_float2(v6, v6);
                float v7 = rwb.w*rs; c0[7*160] = make_float2(v7, v7);
            }
        }
    }

    // epilogue: unpack (b-lo, b-hi) rows and store 5 float2 per row
    float* dst = g_part + (size_t)ks*BB*CO;
    #pragma unroll
    for (int bp = 0; bp < 4; bp++) {
        float lo[10], hi[10];
        #pragma unroll
        for (int j = 0; j < 10; j++) unpack2(acc[bp][j], &lo[j], &hi[j]);
        float* ra = dst + (size_t)(b0 + xb0 + 2*bp)*CO + wc0;
        float* rb = ra + CO;
        #pragma unroll
        for (int u = 0; u < 5; u++) {
            *(float2*)(ra + 2*u) = make_float2(lo[2*u], lo[2*u+1]);
            *(float2*)(rb + 2*u) = make_float2(hi[2*u], hi[2*u+1]);
        }
    }
}

// ---------------------------------------------------------------------------
// reduce split-K partials, squash -> g_V2 (splatted) + final output
// grid 160 x 256: 64 f4 per block, 4-way p-split + smem tree
// ---------------------------------------------------------------------------
__global__ void __launch_bounds__(256) k_sqreduce(float* __restrict__ out,
                                                  int write_out) {
    __shared__ float4 red[256];
    int t = threadIdx.x;
    int i4 = t & 63, pg = t >> 6;
    int idx4 = blockIdx.x * 64 + i4;
    float4 s = make_float4(0,0,0,0);
    #pragma unroll 6
    for (int p = pg*36; p < (pg+1)*36; p++) {
        float4 v = *(const float4*)(g_part + (size_t)p*BB*CO + (size_t)idx4*4);
        s.x += v.x; s.y += v.y; s.z += v.z; s.w += v.w;
    }
    red[t] = s;
    __syncthreads();
    if (t < 64) {
        float4 a = red[t], b = red[t+64], c = red[t+128], d = red[t+192];
        s.x = (a.x + b.x) + (c.x + d.x);
        s.y = (a.y + b.y) + (c.y + d.y);
        s.z = (a.z + b.z) + (c.z + d.z);
        s.w = (a.w + b.w) + (c.w + d.w);
        float4 q;
        q.x = squashf(s.x); q.y = squashf(s.y);
        q.z = squashf(s.z); q.w = squashf(s.w);
        *(float4*)(g_V2 + (size_t)idx4*8)     = make_float4(q.x, q.x, q.y, q.y);
        *(float4*)(g_V2 + (size_t)idx4*8 + 4) = make_float4(q.z, q.z, q.w, q.w);
        if (write_out) *(float4*)(out + (size_t)idx4*4) = q;
    }
}

// ---------------------------------------------------------------------------
// agree: partial G[k,co] = sum_{b half} x[b,k]*V[b,co]; contract with W,
// atomicAdd logits. grid (144, 2), 2 CTAs/SM.
// f32x2 pairs over k (natural from x rows); V pre-splatted in g_V2.
// Inner loop per b: 1 LDS.128(x) + 5 LDS.128(Vsplat) + 20 FFMA2.
// ---------------------------------------------------------------------------
__global__ void __launch_bounds__(256, 2) k_agree(const float* __restrict__ x,
                                                  const float* __restrict__ W) {
    __shared__ __align__(16) float sm[32*320 + 32*64];  // 48 KB; reused as sG
    float* sVs = sm;            // [32][320] splatted V
    float* sXa = sm + 32*320;   // [32][64]  x chunk, k-contiguous

    int t = threadIdx.x;
    int w = t >> 5, l = t & 31;
    int wk = w >> 2, wc = w & 3;
    int lk = l >> 2, lc = l & 3;
    int r0 = blockIdx.x * 8;
    int k0 = r0 * 8;
    int klq = wk*32 + lk*4;        // 4 k = 2 natural pairs
    int wc0 = wc*40 + lc*10;       // 10 co

    ull acc[2][10];
    #pragma unroll
    for (int kp = 0; kp < 2; kp++)
        #pragma unroll
        for (int j = 0; j < 10; j++) acc[kp][j] = 0ull;

    for (int sub = 0; sub < 4; sub++) {
        int bs0 = blockIdx.y * 128 + sub * 32;
        __syncthreads();
        // stage splatted V: 2560 f4, straight copy
        #pragma unroll
        for (int q = 0; q < 10; q++) {
            int idx = t + q*256;
            *(float4*)&sVs[idx*4] =
                *(const float4*)(g_V2 + (size_t)bs0*320 + (size_t)idx*4);
        }
        // stage x chunk: straight f4 copy, k-contiguous rows
        #pragma unroll
        for (int q = 0; q < 2; q++) {
            int idx = t + q*256;
            int bb = idx >> 4, c4 = idx & 15;
            *(float4*)&sXa[bb*64 + c4*4] =
                *(const float4*)(x + (size_t)(bs0+bb)*KK + k0 + c4*4);
        }
        __syncthreads();

        #pragma unroll 2
        for (int b = 0; b < 32; b++) {
            ulonglong2 xq = *(const ulonglong2*)&sXa[b*64 + klq];
            ull xp[2] = {xq.x, xq.y};
            ull vv[10];
            const float* vrow = &sVs[b*320 + 2*wc0];
            #pragma unroll
            for (int u = 0; u < 5; u++) {
                ulonglong2 vq = *(const ulonglong2*)(vrow + 4*u);
                vv[2*u] = vq.x; vv[2*u+1] = vq.y;
            }
            #pragma unroll
            for (int kp = 0; kp < 2; kp++)
                #pragma unroll
                for (int j = 0; j < 10; j++)
                    acc[kp][j] = ffma2(xp[kp], vv[j], acc[kp][j]);
        }
    }
    __syncthreads();

    // spill partial G: sG[k][co], stride 162 (k-lo/hi from pairs)
    #pragma unroll
    for (int kp = 0; kp < 2; kp++)
        #pragma unroll
        for (int j = 0; j < 10; j++) {
            float lo, hi;
            unpack2(acc[kp][j], &lo, &hi);
            sm[(klq + 2*kp    )*162 + wc0 + j] = lo;
            sm[(klq + 2*kp + 1)*162 + wc0 + j] = hi;
        }
    __syncthreads();

    // contraction: warp w -> route r0+w
    int r = r0 + w;
    const float* G = &sm[(w*8)*162];
    for (int c = 0; c < CC; c++) {
        float4 w4 = *(const float4*)(W + ((size_t)r*CC + c)*OO*II + 4*l);
        int e0 = 4*l;
        float p = w4.x * G[((e0  )&7)*162 + c*16 + ((e0  )>>3)]
                + w4.y * G[((e0+1)&7)*162 + c*16 + ((e0+1)>>3)]
                + w4.z * G[((e0+2)&7)*162 + c*16 + ((e0+2)>>3)]
                + w4.w * G[((e0+3)&7)*162 + c*16 + ((e0+3)>>3)];
        #pragma unroll
        for (int off = 16; off; off >>= 1)
            p += __shfl_xor_sync(0xffffffffu, p, off);
        if (l == 0) atomicAdd(&g_b[c*RR + r], p * (1.0f / (float)BB));
    }
}

// ---------------------------------------------------------------------------
// softmax over routes per class ([c][r] layout)
// ---------------------------------------------------------------------------
__global__ void __launch_bounds__(256) k_softmax() {
    int c = blockIdx.x, t = threadIdx.x;
    __shared__ float red[8];

    float v[5];
    #pragma unroll
    for (int q = 0; q < 5; q++) {
        int r = t + q*256;
        v[q] = (r < RR) ? g_b[c*RR + r] : -1e30f;
    }
    float m = fmaxf(fmaxf(fmaxf(v[0], v[1]), fmaxf(v[2], v[3])), v[4]);
    #pragma unroll
    for (int off = 16; off; off >>= 1) m = fmaxf(m, __shfl_xor_sync(~0u, m, off));
    if ((t & 31) == 0) red[t >> 5] = m;
    __syncthreads();
    m = red[0];
    #pragma unroll
    for (int q = 1; q < 8; q++) m = fmaxf(m, red[q]);

    float e[5], sum = 0.0f;
    #pragma unroll
    for (int q = 0; q < 5; q++) {
        int r = t + q*256;
        e[q] = (r < RR) ? __expf(v[q] - m) : 0.0f;
        sum += e[q];
    }
    #pragma unroll
    for (int off = 16; off; off >>= 1) sum += __shfl_xor_sync(~0u, sum, off);
    __syncthreads();
    if ((t & 31) == 0) red[t >> 5] = sum;
    __syncthreads();
    sum = 0.0f;
    #pragma unroll
    for (int q = 0; q < 8; q++) sum += red[q];
    float inv = 1.0f / sum;

    #pragma unroll
    for (int q = 0; q < 5; q++) {
        int r = t + q*256;
        if (r < RR) g_c[c*RR + r] = e[q] * inv;
    }
}

// ---------------------------------------------------------------------------
extern "C" void kernel_launch(void* const* d_in, const int* in_sizes, int n_in,
                              void* d_out, int out_size) {
    const float* x = (const float*)d_in[0];
    const float* W = (const float*)d_in[1];
    if (in_sizes[0] == RR*CC*OO*II && in_sizes[1] == BB*RR*II) {
        W = (const float*)d_in[0];
        x = (const float*)d_in[1];
    }
    float* out = (float*)d_out;

    k_prep<<<dim3(144, 4), 256>>>(x);
    for (int it = 0; it < NITER; it++) {
        k_spart<<<dim3(KSPLIT, 2), 256>>>(W);
        k_sqreduce<<<160, 256>>>(out, it == NITER - 1 ? 1 : 0);
        if (it < NITER - 1) {
            k_agree<<<dim3(144, 2), 256>>>(x, W);
            k_softmax<<<CC, 256>>>();
        }
    }
}

// round 8
// speedup vs baseline: 1.1850x; 1.1783x over previous
#include <cuda_runtime.h>

#define BB 256
#define RR 1152
#define CC 10
#define OO 16
#define II 8
#define CO 160            // CC*OO
#define KK (RR*II)        // 9216
#define NITER 3
#define KSPLIT 144        // k_spart: K chunks of 64 k (8 r)

typedef unsigned long long ull;

__device__ float g_xT[KK*BB];            // x transposed [k][b]
__device__ float g_b[CC*RR];             // logits [c][r]
__device__ float g_c[CC*RR];             // couplings [c][r]
__device__ float g_part[KSPLIT*BB*CO];   // split-K partials of S (23.6 MB)
__device__ float g_V[BB*CO];             // squashed v [b][co]

// ---------------- f32x2 helpers --------------------------------------------
__device__ __forceinline__ ull ffma2(ull a, ull b, ull c) {
    ull d;
    asm("fma.rn.f32x2 %0, %1, %2, %3;" : "=l"(d) : "l"(a), "l"(b), "l"(c));
    return d;
}
__device__ __forceinline__ ull splat2(float x) {
    ull d; unsigned u = __float_as_uint(x);
    asm("mov.b64 %0, {%1, %1};" : "=l"(d) : "r"(u));
    return d;
}
__device__ __forceinline__ float squashf(float s) {
    return s * fabsf(s) / (1.0f + s*s);
}

// ---------------------------------------------------------------------------
// prep: transpose x[b][k] -> xT[k][b] + init logits/couplings
// ---------------------------------------------------------------------------
__global__ void __launch_bounds__(256) k_prep(const float* __restrict__ x) {
    __shared__ float tile[64][66];
    int t = threadIdx.x;
    int k0 = blockIdx.x * 64, b0 = blockIdx.y * 64;

    #pragma unroll
    for (int j = 0; j < 4; j++) {
        int idx = t + j*256;
        int bb = idx >> 4, c4 = idx & 15;
        float4 v = *(const float4*)(x + (size_t)(b0+bb)*KK + k0 + c4*4);
        tile[c4*4+0][bb] = v.x; tile[c4*4+1][bb] = v.y;
        tile[c4*4+2][bb] = v.z; tile[c4*4+3][bb] = v.w;
    }
    __syncthreads();
    #pragma unroll
    for (int j = 0; j < 4; j++) {
        int idx = t + j*256;
        int kk = idx >> 4, b4 = idx & 15;
        float4 v;
        v.x = tile[kk][b4*4+0]; v.y = tile[kk][b4*4+1];
        v.z = tile[kk][b4*4+2]; v.w = tile[kk][b4*4+3];
        *(float4*)(g_xT + (size_t)(k0+kk)*BB + b0 + b4*4) = v;
    }
    int id = (blockIdx.y * 144 + blockIdx.x) * 256 + t;
    if (id < CC*RR) { g_b[id] = 0.0f; g_c[id] = 1.0f / (float)RR; }
}

// ---------------------------------------------------------------------------
// s GEMM partials: part[ks][b][co] = sum_{k in 64-chunk} (cW)[k,co]*xT[k,b]
// grid (144, 2), 2 CTAs/SM. Block tile 128b x 160co, 8 double-buffered
// stages of 8 k. R3 inner engine: natural x tiles, register splat,
// per k-step 2 LDS.128(x) + 5 LDS.64(W) + 8 MOV + 40 FFMA2.
// ---------------------------------------------------------------------------
__global__ void __launch_bounds__(256, 2) k_spart(const float* __restrict__ W) {
    __shared__ __align__(16) float sX[2][8][128];    // x, natural b-major
    __shared__ __align__(16) float sW[2][8][160];    // W scaled by coupling
    __shared__ float sc[80];

    int t = threadIdx.x;
    int w = t >> 5, l = t & 31;
    int wb = w >> 2, wc = w & 3;
    int lb = l >> 2, lc = l & 3;
    int ks = blockIdx.x, bt = blockIdx.y;
    int r0 = ks * 8;
    int b0 = bt * 128;
    int xb0 = wb*64 + lb*8;          // first of 8 b
    int wc0 = wc*40 + lc*10;         // first of 10 co

    if (t < 80) sc[t] = g_c[(t % 10)*RR + r0 + (t / 10)];

    int kl = t >> 5, b4 = t & 31;    // staging roles
    float4 rx, rwa, rwb;
    float  rs = 0.0f;

    __syncthreads();   // sc ready

    // prologue: load + commit stage 0
    rx = *(const float4*)(g_xT + (size_t)(r0*8 + kl)*BB + b0 + b4*4);
    if (t < 160) {
        const float* wp = W + ((size_t)r0*CO + t)*II;
        rwa = *(const float4*)(wp);
        rwb = *(const float4*)(wp + 4);
        rs  = sc[t >> 4];
    }
    *(float4*)&sX[0][kl][b4*4] = rx;
    if (t < 160) {
        sW[0][0][t] = rwa.x*rs; sW[0][1][t] = rwa.y*rs;
        sW[0][2][t] = rwa.z*rs; sW[0][3][t] = rwa.w*rs;
        sW[0][4][t] = rwb.x*rs; sW[0][5][t] = rwb.y*rs;
        sW[0][6][t] = rwb.z*rs; sW[0][7][t] = rwb.w*rs;
    }

    ull acc[8][5];
    #pragma unroll
    for (int bi = 0; bi < 8; bi++)
        #pragma unroll
        for (int j = 0; j < 5; j++) acc[bi][j] = 0ull;

    for (int s = 0; s < 8; s++) {
        int p = s & 1;
        if (s < 7) {   // prefetch stage s+1 into regs
            int r = r0 + s + 1;
            rx = *(const float4*)(g_xT + (size_t)(r*8 + kl)*BB + b0 + b4*4);
            if (t < 160) {
                const float* wp = W + ((size_t)r*CO + t)*II;
                rwa = *(const float4*)(wp);
                rwb = *(const float4*)(wp + 4);
                rs  = sc[(s+1)*10 + (t >> 4)];
            }
        }
        __syncthreads();   // stage s visible

        #pragma unroll
        for (int kk = 0; kk < 8; kk++) {
            float xv[8];
            *(float4*)&xv[0] = *(const float4*)&sX[p][kk][xb0];
            *(float4*)&xv[4] = *(const float4*)&sX[p][kk][xb0 + 4];
            ull wv[5];
            const float* wrow = &sW[p][kk][wc0];
            #pragma unroll
            for (int j = 0; j < 5; j++) wv[j] = *(const ull*)(wrow + 2*j);
            #pragma unroll
            for (int bi = 0; bi < 8; bi++) {
                ull xs = splat2(xv[bi]);
                #pragma unroll
                for (int j = 0; j < 5; j++)
                    acc[bi][j] = ffma2(wv[j], xs, acc[bi][j]);
            }
        }

        if (s < 7) {   // commit prefetched stage
            int q = (s + 1) & 1;
            *(float4*)&sX[q][kl][b4*4] = rx;
            if (t < 160) {
                sW[q][0][t] = rwa.x*rs; sW[q][1][t] = rwa.y*rs;
                sW[q][2][t] = rwa.z*rs; sW[q][3][t] = rwa.w*rs;
                sW[q][4][t] = rwb.x*rs; sW[q][5][t] = rwb.y*rs;
                sW[q][6][t] = rwb.z*rs; sW[q][7][t] = rwb.w*rs;
            }
        }
    }

    // write partials (acc pairs are over contiguous co -> plain ull stores)
    float* dst = g_part + (size_t)ks*BB*CO;
    #pragma unroll
    for (int bi = 0; bi < 8; bi++) {
        float* row = dst + (size_t)(b0 + xb0 + bi)*CO + wc0;
        #pragma unroll
        for (int j = 0; j < 5; j++) *(ull*)(row + 2*j) = acc[bi][j];
    }
}

// ---------------------------------------------------------------------------
// reduce split-K partials, squash -> g_V (+ final output)
// grid 160 x 256: 64 f4 per block, 4-way p-split + smem tree
// ---------------------------------------------------------------------------
__global__ void __launch_bounds__(256) k_sqreduce(float* __restrict__ out,
                                                  int write_out) {
    __shared__ float4 red[256];
    int t = threadIdx.x;
    int i4 = t & 63, pg = t >> 6;
    int idx4 = blockIdx.x * 64 + i4;
    float4 s = make_float4(0,0,0,0);
    #pragma unroll 6
    for (int p = pg*36; p < (pg+1)*36; p++) {
        float4 v = *(const float4*)(g_part + (size_t)p*BB*CO + (size_t)idx4*4);
        s.x += v.x; s.y += v.y; s.z += v.z; s.w += v.w;
    }
    red[t] = s;
    __syncthreads();
    if (t < 64) {
        float4 a = red[t], b = red[t+64], c = red[t+128], d = red[t+192];
        s.x = (a.x + b.x) + (c.x + d.x);
        s.y = (a.y + b.y) + (c.y + d.y);
        s.z = (a.z + b.z) + (c.z + d.z);
        s.w = (a.w + b.w) + (c.w + d.w);
        float4 q;
        q.x = squashf(s.x); q.y = squashf(s.y);
        q.z = squashf(s.z); q.w = squashf(s.w);
        *(float4*)(g_V + (size_t)idx4*4) = q;
        if (write_out) *(float4*)(out + (size_t)idx4*4) = q;
    }
}

// ---------------------------------------------------------------------------
// agree: partial G[k,co] = sum_{b half} xT[k,b]*V[b,co]; contract with W,
// atomicAdd logits. grid (144, 2), 2 CTAs/SM. R3 engine, no smem splat.
// ---------------------------------------------------------------------------
__global__ void __launch_bounds__(256, 2) k_agree(const float* __restrict__ W) {
    __shared__ __align__(16) float sm[64*162];   // 41.5 KB (reused as sG)
    float* sV  = sm;          // [32][160] = 5120
    float* sXa = sm + 5120;   // [32][68]  = 2176

    int t = threadIdx.x;
    int w = t >> 5, l = t & 31;
    int wk = w >> 2, wc = w & 3;
    int lk = l >> 2, lc = l & 3;
    int r0 = blockIdx.x * 8;
    int k0 = r0 * 8;
    int klq = wk*32 + lk*4;        // 4 k per lane
    int wc0 = wc*40 + lc*10;       // 10 co per lane

    ull acc[4][5];
    #pragma unroll
    for (int ki = 0; ki < 4; ki++)
        #pragma unroll
        for (int j = 0; j < 5; j++) acc[ki][j] = 0ull;

    for (int sub = 0; sub < 4; sub++) {
        int bs0 = blockIdx.y * 128 + sub * 32;
        __syncthreads();
        // stage V: 1280 f4 coalesced
        #pragma unroll
        for (int q = 0; q < 5; q++) {
            int idx = t + q*256;
            *(float4*)&sV[idx*4] =
                *(const float4*)(g_V + (size_t)bs0*CO + (size_t)idx*4);
        }
        // stage xT chunk: 64 k x 32 b -> sXa[b][k] (stride 68)
        #pragma unroll
        for (int q = 0; q < 2; q++) {
            int idx = t + q*256;
            int kl = idx >> 3, bb = idx & 7;
            float4 v = *(const float4*)(g_xT + (size_t)(k0+kl)*BB + bs0 + bb*4);
            sXa[(bb*4+0)*68 + kl] = v.x; sXa[(bb*4+1)*68 + kl] = v.y;
            sXa[(bb*4+2)*68 + kl] = v.z; sXa[(bb*4+3)*68 + kl] = v.w;
        }
        __syncthreads();

        #pragma unroll 2
        for (int b = 0; b < 32; b++) {
            float4 xk = *(const float4*)&sXa[b*68 + klq];
            ull vv[5];
            const float* vrow = &sV[b*160 + wc0];
            #pragma unroll
            for (int j = 0; j < 5; j++) vv[j] = *(const ull*)(vrow + 2*j);
            ull xs0 = splat2(xk.x), xs1 = splat2(xk.y);
            ull xs2 = splat2(xk.z), xs3 = splat2(xk.w);
            #pragma unroll
            for (int j = 0; j < 5; j++) {
                acc[0][j] = ffma2(vv[j], xs0, acc[0][j]);
                acc[1][j] = ffma2(vv[j], xs1, acc[1][j]);
                acc[2][j] = ffma2(vv[j], xs2, acc[2][j]);
                acc[3][j] = ffma2(vv[j], xs3, acc[3][j]);
            }
        }
    }
    __syncthreads();

    // spill partial G: sG[k][co], stride 162
    #pragma unroll
    for (int ki = 0; ki < 4; ki++)
        #pragma unroll
        for (int j = 0; j < 5; j++)
            *(ull*)&sm[(klq + ki)*162 + wc0 + 2*j] = acc[ki][j];
    __syncthreads();

    // contraction: warp w -> route r0+w
    int r = r0 + w;
    const float* G = &sm[(w*8)*162];
    for (int c = 0; c < CC; c++) {
        float4 w4 = *(const float4*)(W + ((size_t)r*CC + c)*OO*II + 4*l);
        int e0 = 4*l;
        float p = w4.x * G[((e0  )&7)*162 + c*16 + ((e0  )>>3)]
                + w4.y * G[((e0+1)&7)*162 + c*16 + ((e0+1)>>3)]
                + w4.z * G[((e0+2)&7)*162 + c*16 + ((e0+2)>>3)]
                + w4.w * G[((e0+3)&7)*162 + c*16 + ((e0+3)>>3)];
        #pragma unroll
        for (int off = 16; off; off >>= 1)
            p += __shfl_xor_sync(0xffffffffu, p, off);
        if (l == 0) atomicAdd(&g_b[c*RR + r], p * (1.0f / (float)BB));
    }
}

// ---------------------------------------------------------------------------
// softmax over routes per class ([c][r] layout)
// ---------------------------------------------------------------------------
__global__ void __launch_bounds__(256) k_softmax() {
    int c = blockIdx.x, t = threadIdx.x;
    __shared__ float red[8];

    float v[5];
    #pragma unroll
    for (int q = 0; q < 5; q++) {
        int r = t + q*256;
        v[q] = (r < RR) ? g_b[c*RR + r] : -1e30f;
    }
    float m = fmaxf(fmaxf(fmaxf(v[0], v[1]), fmaxf(v[2], v[3])), v[4]);
    #pragma unroll
    for (int off = 16; off; off >>= 1) m = fmaxf(m, __shfl_xor_sync(~0u, m, off));
    if ((t & 31) == 0) red[t >> 5] = m;
    __syncthreads();
    m = red[0];
    #pragma unroll
    for (int q = 1; q < 8; q++) m = fmaxf(m, red[q]);

    float e[5], sum = 0.0f;
    #pragma unroll
    for (int q = 0; q < 5; q++) {
        int r = t + q*256;
        e[q] = (r < RR) ? __expf(v[q] - m) : 0.0f;
        sum += e[q];
    }
    #pragma unroll
    for (int off = 16; off; off >>= 1) sum += __shfl_xor_sync(~0u, sum, off);
    __syncthreads();
    if ((t & 31) == 0) red[t >> 5] = sum;
    __syncthreads();
    sum = 0.0f;
    #pragma unroll
    for (int q = 0; q < 8; q++) sum += red[q];
    float inv = 1.0f / sum;

    #pragma unroll
    for (int q = 0; q < 5; q++) {
        int r = t + q*256;
        if (r < RR) g_c[c*RR + r] = e[q] * inv;
    }
}

// ---------------------------------------------------------------------------
extern "C" void kernel_launch(void* const* d_in, const int* in_sizes, int n_in,
                              void* d_out, int out_size) {
    const float* x = (const float*)d_in[0];
    const float* W = (const float*)d_in[1];
    if (in_sizes[0] == RR*CC*OO*II && in_sizes[1] == BB*RR*II) {
        W = (const float*)d_in[0];
        x = (const float*)d_in[1];
    }
    float* out = (float*)d_out;

    k_prep<<<dim3(144, 4), 256>>>(x);
    for (int it = 0; it < NITER; it++) {
        k_spart<<<dim3(KSPLIT, 2), 256>>>(W);
        k_sqreduce<<<160, 256>>>(out, it == NITER - 1 ? 1 : 0);
        if (it < NITER - 1) {
            k_agree<<<dim3(144, 2), 256>>>(W);
            k_softmax<<<CC, 256>>>();
        }
    }
}

// round 9
// speedup vs baseline: 1.1852x; 1.0002x over previous
#include <cuda_runtime.h>

#define BB 256
#define RR 1152
#define CC 10
#define OO 16
#define II 8
#define CO 160            // CC*OO
#define KK (RR*II)        // 9216
#define NITER 3
#define KSPLIT 144        // k_spart: K chunks of 64 k (8 r)

typedef unsigned long long ull;

__device__ float g_xT[KK*BB];            // x transposed [k][b]
__device__ float g_b[CC*RR];             // logits [c][r]
__device__ float g_c[CC*RR];             // couplings [c][r]
__device__ float g_part[KSPLIT*BB*CO];   // split-K partials of S (23.6 MB)
__device__ float g_V[BB*CO];             // squashed v [b][co]

// ---------------- f32x2 helpers --------------------------------------------
__device__ __forceinline__ ull ffma2(ull a, ull b, ull c) {
    ull d;
    asm("fma.rn.f32x2 %0, %1, %2, %3;" : "=l"(d) : "l"(a), "l"(b), "l"(c));
    return d;
}
__device__ __forceinline__ ull splat2(float x) {
    ull d; unsigned u = __float_as_uint(x);
    asm("mov.b64 %0, {%1, %1};" : "=l"(d) : "r"(u));
    return d;
}
__device__ __forceinline__ float squashf(float s) {
    return s * fabsf(s) / (1.0f + s*s);
}

// ---------------------------------------------------------------------------
// prep: transpose x[b][k] -> xT[k][b] + init logits/couplings
// ---------------------------------------------------------------------------
__global__ void __launch_bounds__(256) k_prep(const float* __restrict__ x) {
    __shared__ float tile[64][66];
    int t = threadIdx.x;
    int k0 = blockIdx.x * 64, b0 = blockIdx.y * 64;

    #pragma unroll
    for (int j = 0; j < 4; j++) {
        int idx = t + j*256;
        int bb = idx >> 4, c4 = idx & 15;
        float4 v = *(const float4*)(x + (size_t)(b0+bb)*KK + k0 + c4*4);
        tile[c4*4+0][bb] = v.x; tile[c4*4+1][bb] = v.y;
        tile[c4*4+2][bb] = v.z; tile[c4*4+3][bb] = v.w;
    }
    __syncthreads();
    #pragma unroll
    for (int j = 0; j < 4; j++) {
        int idx = t + j*256;
        int kk = idx >> 4, b4 = idx & 15;
        float4 v;
        v.x = tile[kk][b4*4+0]; v.y = tile[kk][b4*4+1];
        v.z = tile[kk][b4*4+2]; v.w = tile[kk][b4*4+3];
        *(float4*)(g_xT + (size_t)(k0+kk)*BB + b0 + b4*4) = v;
    }
    int id = (blockIdx.y * 144 + blockIdx.x) * 256 + t;
    if (id < CC*RR) { g_b[id] = 0.0f; g_c[id] = 1.0f / (float)RR; }
}

// ---------------------------------------------------------------------------
// s GEMM partials: part[ks][b][co] += sum_{k in 64-chunk} (cW)[k,co]*xT[k,b]
// grid (144, 4, 2): 128 threads, tile 64b x 80co, ~6 CTAs/SM.
// lane tile 4b x 10co: per k-step 1 LDS.128 + 5 LDS.64 + 4 splat + 20 FFMA2.
// ---------------------------------------------------------------------------
__global__ void __launch_bounds__(128, 4) k_spart(const float* __restrict__ W) {
    __shared__ __align__(16) float sX[2][8][64];
    __shared__ __align__(16) float sW[2][8][80];
    __shared__ float sc[80];

    int t = threadIdx.x;
    int w = t >> 5, l = t & 31;
    int lb = l >> 1, lc = l & 1;
    int ks = blockIdx.x, bt = blockIdx.y, ct = blockIdx.z;
    int r0 = ks * 8;
    int b0 = bt * 64;
    int co0 = ct * 80;
    int xb0 = lb * 4;                 // 4 b per lane
    int wcl = w*20 + lc*10;           // local co (within 80)

    if (t < 80) sc[t] = g_c[(t % 10)*RR + r0 + (t / 10)];

    int kl = t >> 4, b4 = t & 15;     // x staging role (128 f4)
    int wco = co0 + t;                // W staging role (t < 80)
    float4 rx, rwa, rwb;
    float  rs = 0.0f;

    __syncthreads();   // sc ready

    // prologue: load + commit stage 0
    rx = *(const float4*)(g_xT + (size_t)(r0*8 + kl)*BB + b0 + b4*4);
    if (t < 80) {
        const float* wp = W + ((size_t)r0*CO + wco)*II;
        rwa = *(const float4*)(wp);
        rwb = *(const float4*)(wp + 4);
        rs  = sc[wco >> 4];
    }
    *(float4*)&sX[0][kl][b4*4] = rx;
    if (t < 80) {
        sW[0][0][t] = rwa.x*rs; sW[0][1][t] = rwa.y*rs;
        sW[0][2][t] = rwa.z*rs; sW[0][3][t] = rwa.w*rs;
        sW[0][4][t] = rwb.x*rs; sW[0][5][t] = rwb.y*rs;
        sW[0][6][t] = rwb.z*rs; sW[0][7][t] = rwb.w*rs;
    }

    ull acc[4][5];
    #pragma unroll
    for (int bi = 0; bi < 4; bi++)
        #pragma unroll
        for (int j = 0; j < 5; j++) acc[bi][j] = 0ull;

    for (int s = 0; s < 8; s++) {
        int p = s & 1;
        if (s < 7) {   // prefetch stage s+1
            int r = r0 + s + 1;
            rx = *(const float4*)(g_xT + (size_t)(r*8 + kl)*BB + b0 + b4*4);
            if (t < 80) {
                const float* wp = W + ((size_t)r*CO + wco)*II;
                rwa = *(const float4*)(wp);
                rwb = *(const float4*)(wp + 4);
                rs  = sc[(s+1)*10 + (wco >> 4)];
            }
        }
        __syncthreads();

        #pragma unroll
        for (int kk = 0; kk < 8; kk++) {
            float4 xq = *(const float4*)&sX[p][kk][xb0];
            ull wv[5];
            const float* wrow = &sW[p][kk][wcl];
            #pragma unroll
            for (int j = 0; j < 5; j++) wv[j] = *(const ull*)(wrow + 2*j);
            ull xs0 = splat2(xq.x), xs1 = splat2(xq.y);
            ull xs2 = splat2(xq.z), xs3 = splat2(xq.w);
            #pragma unroll
            for (int j = 0; j < 5; j++) {
                acc[0][j] = ffma2(wv[j], xs0, acc[0][j]);
                acc[1][j] = ffma2(wv[j], xs1, acc[1][j]);
                acc[2][j] = ffma2(wv[j], xs2, acc[2][j]);
                acc[3][j] = ffma2(wv[j], xs3, acc[3][j]);
            }
        }

        if (s < 7) {   // commit prefetched stage
            int q = (s + 1) & 1;
            *(float4*)&sX[q][kl][b4*4] = rx;
            if (t < 80) {
                sW[q][0][t] = rwa.x*rs; sW[q][1][t] = rwa.y*rs;
                sW[q][2][t] = rwa.z*rs; sW[q][3][t] = rwa.w*rs;
                sW[q][4][t] = rwb.x*rs; sW[q][5][t] = rwb.y*rs;
                sW[q][6][t] = rwb.z*rs; sW[q][7][t] = rwb.w*rs;
            }
        }
    }

    // write partials (pairs over contiguous co -> plain ull stores)
    float* dst = g_part + (size_t)ks*BB*CO;
    #pragma unroll
    for (int bi = 0; bi < 4; bi++) {
        float* row = dst + (size_t)(b0 + xb0 + bi)*CO + co0 + wcl;
        #pragma unroll
        for (int j = 0; j < 5; j++) *(ull*)(row + 2*j) = acc[bi][j];
    }
}

// ---------------------------------------------------------------------------
// reduce split-K partials, squash -> g_V (+ final output)
// grid 160 x 256: 64 f4 per block, 4-way p-split + smem tree
// ---------------------------------------------------------------------------
__global__ void __launch_bounds__(256) k_sqreduce(float* __restrict__ out,
                                                  int write_out) {
    __shared__ float4 red[256];
    int t = threadIdx.x;
    int i4 = t & 63, pg = t >> 6;
    int idx4 = blockIdx.x * 64 + i4;
    float4 s = make_float4(0,0,0,0);
    #pragma unroll 6
    for (int p = pg*36; p < (pg+1)*36; p++) {
        float4 v = *(const float4*)(g_part + (size_t)p*BB*CO + (size_t)idx4*4);
        s.x += v.x; s.y += v.y; s.z += v.z; s.w += v.w;
    }
    red[t] = s;
    __syncthreads();
    if (t < 64) {
        float4 a = red[t], b = red[t+64], c = red[t+128], d = red[t+192];
        s.x = (a.x + b.x) + (c.x + d.x);
        s.y = (a.y + b.y) + (c.y + d.y);
        s.z = (a.z + b.z) + (c.z + d.z);
        s.w = (a.w + b.w) + (c.w + d.w);
        float4 q;
        q.x = squashf(s.x); q.y = squashf(s.y);
        q.z = squashf(s.z); q.w = squashf(s.w);
        *(float4*)(g_V + (size_t)idx4*4) = q;
        if (write_out) *(float4*)(out + (size_t)idx4*4) = q;
    }
}

// ---------------------------------------------------------------------------
// agree: partial G[k,co] = sum_{b quarter} xT[k,b]*V[b,co]; contract with W,
// atomicAdd logits. grid (288, 4): 128 threads, 4 routes (32 k) per CTA.
// ---------------------------------------------------------------------------
__global__ void __launch_bounds__(128, 4) k_agree(const float* __restrict__ W) {
    __shared__ __align__(16) float sm[6272];   // 24.5 KB (reused as sG 32x162)
    float* sV  = sm;          // [32][160] = 5120
    float* sXa = sm + 5120;   // [32][36]  = 1152

    int t = threadIdx.x;
    int w = t >> 5, l = t & 31;
    int r0 = blockIdx.x * 4;       // 4 routes
    int k0 = r0 * 8;               // 32 k
    int klq = (l >> 2) * 4;        // 4 k per lane
    int wc0 = w*40 + (l & 3)*10;   // 10 co per lane

    ull acc[4][5];
    #pragma unroll
    for (int ki = 0; ki < 4; ki++)
        #pragma unroll
        for (int j = 0; j < 5; j++) acc[ki][j] = 0ull;

    for (int sub = 0; sub < 2; sub++) {
        int bs0 = blockIdx.y * 64 + sub * 32;
        __syncthreads();
        // stage V: 1280 f4 coalesced (10 per thread)
        #pragma unroll
        for (int q = 0; q < 10; q++) {
            int idx = t + q*128;
            *(float4*)&sV[idx*4] =
                *(const float4*)(g_V + (size_t)bs0*CO + (size_t)idx*4);
        }
        // stage xT chunk: 32 k x 32 b -> sXa[b][k] (stride 36)
        #pragma unroll
        for (int q = 0; q < 2; q++) {
            int idx = t + q*128;            // 0..255
            int kl = idx >> 3, bb = idx & 7;
            float4 v = *(const float4*)(g_xT + (size_t)(k0+kl)*BB + bs0 + bb*4);
            sXa[(bb*4+0)*36 + kl] = v.x; sXa[(bb*4+1)*36 + kl] = v.y;
            sXa[(bb*4+2)*36 + kl] = v.z; sXa[(bb*4+3)*36 + kl] = v.w;
        }
        __syncthreads();

        #pragma unroll 2
        for (int b = 0; b < 32; b++) {
            float4 xk = *(const float4*)&sXa[b*36 + klq];
            ull vv[5];
            const float* vrow = &sV[b*160 + wc0];
            #pragma unroll
            for (int j = 0; j < 5; j++) vv[j] = *(const ull*)(vrow + 2*j);
            ull xs0 = splat2(xk.x), xs1 = splat2(xk.y);
            ull xs2 = splat2(xk.z), xs3 = splat2(xk.w);
            #pragma unroll
            for (int j = 0; j < 5; j++) {
                acc[0][j] = ffma2(vv[j], xs0, acc[0][j]);
                acc[1][j] = ffma2(vv[j], xs1, acc[1][j]);
                acc[2][j] = ffma2(vv[j], xs2, acc[2][j]);
                acc[3][j] = ffma2(vv[j], xs3, acc[3][j]);
            }
        }
    }
    __syncthreads();

    // spill partial G: sG[k][co], stride 162 (32 rows)
    #pragma unroll
    for (int ki = 0; ki < 4; ki++)
        #pragma unroll
        for (int j = 0; j < 5; j++)
            *(ull*)&sm[(klq + ki)*162 + wc0 + 2*j] = acc[ki][j];
    __syncthreads();

    // contraction: warp w -> route r0+w (4 warps, 4 routes)
    int r = r0 + w;
    const float* G = &sm[(w*8)*162];
    for (int c = 0; c < CC; c++) {
        float4 w4 = *(const float4*)(W + ((size_t)r*CC + c)*OO*II + 4*l);
        int e0 = 4*l;
        float p = w4.x * G[((e0  )&7)*162 + c*16 + ((e0  )>>3)]
                + w4.y * G[((e0+1)&7)*162 + c*16 + ((e0+1)>>3)]
                + w4.z * G[((e0+2)&7)*162 + c*16 + ((e0+2)>>3)]
                + w4.w * G[((e0+3)&7)*162 + c*16 + ((e0+3)>>3)];
        #pragma unroll
        for (int off = 16; off; off >>= 1)
            p += __shfl_xor_sync(0xffffffffu, p, off);
        if (l == 0) atomicAdd(&g_b[c*RR + r], p * (1.0f / (float)BB));
    }
}

// ---------------------------------------------------------------------------
// softmax over routes per class ([c][r] layout)
// ---------------------------------------------------------------------------
__global__ void __launch_bounds__(256) k_softmax() {
    int c = blockIdx.x, t = threadIdx.x;
    __shared__ float red[8];

    float v[5];
    #pragma unroll
    for (int q = 0; q < 5; q++) {
        int r = t + q*256;
        v[q] = (r < RR) ? g_b[c*RR + r] : -1e30f;
    }
    float m = fmaxf(fmaxf(fmaxf(v[0], v[1]), fmaxf(v[2], v[3])), v[4]);
    #pragma unroll
    for (int off = 16; off; off >>= 1) m = fmaxf(m, __shfl_xor_sync(~0u, m, off));
    if ((t & 31) == 0) red[t >> 5] = m;
    __syncthreads();
    m = red[0];
    #pragma unroll
    for (int q = 1; q < 8; q++) m = fmaxf(m, red[q]);

    float e[5], sum = 0.0f;
    #pragma unroll
    for (int q = 0; q < 5; q++) {
        int r = t + q*256;
        e[q] = (r < RR) ? __expf(v[q] - m) : 0.0f;
        sum += e[q];
    }
    #pragma unroll
    for (int off = 16; off; off >>= 1) sum += __shfl_xor_sync(~0u, sum, off);
    __syncthreads();
    if ((t & 31) == 0) red[t >> 5] = sum;
    __syncthreads();
    sum = 0.0f;
    #pragma unroll
    for (int q = 0; q < 8; q++) sum += red[q];
    float inv = 1.0f / sum;

    #pragma unroll
    for (int q = 0; q < 5; q++) {
        int r = t + q*256;
        if (r < RR) g_c[c*RR + r] = e[q] * inv;
    }
}

// ---------------------------------------------------------------------------
extern "C" void kernel_launch(void* const* d_in, const int* in_sizes, int n_in,
                              void* d_out, int out_size) {
    const float* x = (const float*)d_in[0];
    const float* W = (const float*)d_in[1];
    if (in_sizes[0] == RR*CC*OO*II && in_sizes[1] == BB*RR*II) {
        W = (const float*)d_in[0];
        x = (const float*)d_in[1];
    }
    float* out = (float*)d_out;

    k_prep<<<dim3(144, 4), 256>>>(x);
    for (int it = 0; it < NITER; it++) {
        k_spart<<<dim3(KSPLIT, 4, 2), 128>>>(W);
        k_sqreduce<<<160, 256>>>(out, it == NITER - 1 ? 1 : 0);
        if (it < NITER - 1) {
            k_agree<<<dim3(288, 4), 128>>>(W);
            k_softmax<<<CC, 256>>>();
        }
    }
}

// round 10
// speedup vs baseline: 1.4393x; 1.2144x over previous
#include <cuda_runtime.h>

#define BB 256
#define RR 1152
#define CC 10
#define OO 16
#define II 8
#define CO 160            // CC*OO
#define KK (RR*II)        // 9216
#define NITER 3
#define KSPLIT 144        // k_spart: K chunks of 64 k (8 r)

typedef unsigned long long ull;

__device__ float g_b[CC*RR];             // logits [c][r]
__device__ float g_c[CC*RR];             // couplings [c][r]
__device__ float g_part[KSPLIT*BB*CO];   // split-K partials of S
__device__ float g_V[BB*CO];             // squashed v [b][co]

// ---------------- f32x2 helpers --------------------------------------------
__device__ __forceinline__ ull ffma2(ull a, ull b, ull c) {
    ull d;
    asm("fma.rn.f32x2 %0, %1, %2, %3;" : "=l"(d) : "l"(a), "l"(b), "l"(c));
    return d;
}
__device__ __forceinline__ ull splat2(float x) {
    ull d; unsigned u = __float_as_uint(x);
    asm("mov.b64 %0, {%1, %1};" : "=l"(d) : "r"(u));
    return d;
}
__device__ __forceinline__ void unpack2(ull a, float* lo, float* hi) {
    unsigned l_, h_;
    asm("mov.b64 {%0, %1}, %2;" : "=r"(l_), "=r"(h_) : "l"(a));
    *lo = __uint_as_float(l_); *hi = __uint_as_float(h_);
}
__device__ __forceinline__ float squashf(float s) {
    return s * fabsf(s) / (1.0f + s*s);
}

// ---------------------------------------------------------------------------
// s GEMM partials: part[ks][b][co] = sum_{k in 64-chunk} (cW)[k,co]*x[b,k]
// grid (144, 8), 128 thr. Block tile 32b x 160co, 8 double-buffered stages
// of 8 k. Warp w: b rows [w*8, w*8+8), all co. Lane l: co {l+32j}.
// Per k-step: 2 bcast LDS.128 (8b) + 5 coalesced LDS.32 (W) + 5 splat
// + 20 FFMA2. All smem ops are 1 wavefront. x staged straight from input.
// ---------------------------------------------------------------------------
__global__ void __launch_bounds__(128, 5) k_spart(const float* __restrict__ x,
                                                  const float* __restrict__ W,
                                                  int uniform) {
    __shared__ __align__(16) float sX[2][8][32];     // [k][b]
    __shared__ __align__(16) float sW[2][8][160];    // [k][co], c-scaled
    __shared__ float sc[80];

    int t = threadIdx.x;
    int w = t >> 5, l = t & 31;
    int ks = blockIdx.x, bt = blockIdx.y;
    int r0 = ks * 8;
    int b0 = bt * 32;
    int wb = w * 8;                   // warp's local b base

    if (t < 80)
        sc[t] = uniform ? (1.0f / (float)RR)
                        : g_c[(t % 10)*RR + r0 + (t / 10)];

    // staging roles
    int xb = t >> 1, xh = t & 1;      // t<64: local b, k-half
    float4 rx = make_float4(0,0,0,0);
    float4 rwa, rwb, rwc, rwd;
    float rs1 = 0.0f, rs2 = 0.0f;

    __syncthreads();   // sc ready

    // prologue: load stage 0
    if (t < 64)
        rx = *(const float4*)(x + (size_t)(b0+xb)*KK + r0*8 + xh*4);
    {
        const float* wp = W + ((size_t)r0*CO + t)*II;
        rwa = *(const float4*)wp; rwb = *(const float4*)(wp + 4);
        rs1 = sc[t >> 4];
        if (t < 32) {
            const float* wq = W + ((size_t)r0*CO + t + 128)*II;
            rwc = *(const float4*)wq; rwd = *(const float4*)(wq + 4);
            rs2 = sc[(t + 128) >> 4];
        }
    }
    // commit stage 0
    if (t < 64) {
        sX[0][xh*4+0][xb] = rx.x; sX[0][xh*4+1][xb] = rx.y;
        sX[0][xh*4+2][xb] = rx.z; sX[0][xh*4+3][xb] = rx.w;
    }
    sW[0][0][t] = rwa.x*rs1; sW[0][1][t] = rwa.y*rs1;
    sW[0][2][t] = rwa.z*rs1; sW[0][3][t] = rwa.w*rs1;
    sW[0][4][t] = rwb.x*rs1; sW[0][5][t] = rwb.y*rs1;
    sW[0][6][t] = rwb.z*rs1; sW[0][7][t] = rwb.w*rs1;
    if (t < 32) {
        sW[0][0][t+128] = rwc.x*rs2; sW[0][1][t+128] = rwc.y*rs2;
        sW[0][2][t+128] = rwc.z*rs2; sW[0][3][t+128] = rwc.w*rs2;
        sW[0][4][t+128] = rwd.x*rs2; sW[0][5][t+128] = rwd.y*rs2;
        sW[0][6][t+128] = rwd.z*rs2; sW[0][7][t+128] = rwd.w*rs2;
    }

    ull acc[4][5];
    #pragma unroll
    for (int bp = 0; bp < 4; bp++)
        #pragma unroll
        for (int j = 0; j < 5; j++) acc[bp][j] = 0ull;

    for (int s = 0; s < 8; s++) {
        int p = s & 1;
        if (s < 7) {    // prefetch stage s+1
            int r = r0 + s + 1;
            if (t < 64)
                rx = *(const float4*)(x + (size_t)(b0+xb)*KK + r*8 + xh*4);
            const float* wp = W + ((size_t)r*CO + t)*II;
            rwa = *(const float4*)wp; rwb = *(const float4*)(wp + 4);
            rs1 = sc[(s+1)*10 + (t >> 4)];
            if (t < 32) {
                const float* wq = W + ((size_t)r*CO + t + 128)*II;
                rwc = *(const float4*)wq; rwd = *(const float4*)(wq + 4);
                rs2 = sc[(s+1)*10 + ((t + 128) >> 4)];
            }
        }
        __syncthreads();   // stage s visible

        #pragma unroll
        for (int kk = 0; kk < 8; kk++) {
            const float* xr = &sX[p][kk][wb];
            ulonglong2 xa = *(const ulonglong2*)xr;         // b pairs 0,1
            ulonglong2 xc = *(const ulonglong2*)(xr + 4);   // b pairs 2,3
            ull xp[4] = {xa.x, xa.y, xc.x, xc.y};
            const float* wr = &sW[p][kk][l];
            ull ws[5];
            #pragma unroll
            for (int j = 0; j < 5; j++) ws[j] = splat2(wr[32*j]);
            #pragma unroll
            for (int bp = 0; bp < 4; bp++)
                #pragma unroll
                for (int j = 0; j < 5; j++)
                    acc[bp][j] = ffma2(xp[bp], ws[j], acc[bp][j]);
        }

        if (s < 7) {    // commit prefetched stage into the other buffer
            int q = (s + 1) & 1;
            if (t < 64) {
                sX[q][xh*4+0][xb] = rx.x; sX[q][xh*4+1][xb] = rx.y;
                sX[q][xh*4+2][xb] = rx.z; sX[q][xh*4+3][xb] = rx.w;
            }
            sW[q][0][t] = rwa.x*rs1; sW[q][1][t] = rwa.y*rs1;
            sW[q][2][t] = rwa.z*rs1; sW[q][3][t] = rwa.w*rs1;
            sW[q][4][t] = rwb.x*rs1; sW[q][5][t] = rwb.y*rs1;
            sW[q][6][t] = rwb.z*rs1; sW[q][7][t] = rwb.w*rs1;
            if (t < 32) {
                sW[q][0][t+128] = rwc.x*rs2; sW[q][1][t+128] = rwc.y*rs2;
                sW[q][2][t+128] = rwc.z*rs2; sW[q][3][t+128] = rwc.w*rs2;
                sW[q][4][t+128] = rwd.x*rs2; sW[q][5][t+128] = rwd.y*rs2;
                sW[q][6][t+128] = rwd.z*rs2; sW[q][7][t+128] = rwd.w*rs2;
            }
        }
    }

    // epilogue: coalesced scalar stores (lanes = consecutive co)
    float* dst = g_part + (size_t)ks*BB*CO + (size_t)b0*CO;
    #pragma unroll
    for (int bp = 0; bp < 4; bp++) {
        float lo[5], hi[5];
        #pragma unroll
        for (int j = 0; j < 5; j++) unpack2(acc[bp][j], &lo[j], &hi[j]);
        float* ra = dst + (size_t)(wb + 2*bp)*CO + l;
        float* rb = ra + CO;
        #pragma unroll
        for (int j = 0; j < 5; j++) { ra[32*j] = lo[j]; rb[32*j] = hi[j]; }
    }
}

// ---------------------------------------------------------------------------
// reduce split-K partials, squash -> g_V (+ final output); optionally zero g_b
// grid 160 x 256: 64 f4 per block, 4-way p-split + smem tree
// ---------------------------------------------------------------------------
__global__ void __launch_bounds__(256) k_sqreduce(float* __restrict__ out,
                                                  int write_out, int zero_b) {
    __shared__ float4 red[256];
    int t = threadIdx.x;
    if (zero_b) {
        int gid = blockIdx.x * 256 + t;
        if (gid < CC*RR) g_b[gid] = 0.0f;
    }
    int i4 = t & 63, pg = t >> 6;
    int idx4 = blockIdx.x * 64 + i4;
    float4 s = make_float4(0,0,0,0);
    #pragma unroll 6
    for (int p = pg*36; p < (pg+1)*36; p++) {
        float4 v = *(const float4*)(g_part + (size_t)p*BB*CO + (size_t)idx4*4);
        s.x += v.x; s.y += v.y; s.z += v.z; s.w += v.w;
    }
    red[t] = s;
    __syncthreads();
    if (t < 64) {
        float4 a = red[t], b = red[t+64], c = red[t+128], d = red[t+192];
        s.x = (a.x + b.x) + (c.x + d.x);
        s.y = (a.y + b.y) + (c.y + d.y);
        s.z = (a.z + b.z) + (c.z + d.z);
        s.w = (a.w + b.w) + (c.w + d.w);
        float4 q;
        q.x = squashf(s.x); q.y = squashf(s.y);
        q.z = squashf(s.z); q.w = squashf(s.w);
        *(float4*)(g_V + (size_t)idx4*4) = q;
        if (write_out) *(float4*)(out + (size_t)idx4*4) = q;
    }
}

// ---------------------------------------------------------------------------
// agree: partial G[k,co] = sum_{b quarter} x[b,k]*V[b,co]; contract with W,
// atomicAdd logits. grid (288, 4), 128 thr, 4 routes (32 k) per CTA.
// Warp w: k rows [w*8, w*8+8), all co. Lane l: co {l+32j}.
// Per b-step: 2 bcast LDS.128 (8k, natural pairs) + 5 coalesced LDS.32 (V)
// + 5 splat + 20 FFMA2. x staged by direct f4 copy (k-contiguous, no transpose).
// ---------------------------------------------------------------------------
__global__ void __launch_bounds__(128, 5) k_agree(const float* __restrict__ x,
                                                  const float* __restrict__ W) {
    __shared__ __align__(16) float sm[6272];   // reused as sG [32][162]
    float* sV  = sm;          // [32][160] = 5120
    float* sXa = sm + 5120;   // [32][32]  = 1024

    int t = threadIdx.x;
    int w = t >> 5, l = t & 31;
    int r0 = blockIdx.x * 4;       // 4 routes
    int k0 = r0 * 8;               // 32 k
    int wk = w * 8;                // warp's local k base

    ull acc[4][5];                 // 4 k-pairs x 5 strided co
    #pragma unroll
    for (int kp = 0; kp < 4; kp++)
        #pragma unroll
        for (int j = 0; j < 5; j++) acc[kp][j] = 0ull;

    for (int sub = 0; sub < 2; sub++) {
        int bs0 = blockIdx.y * 64 + sub * 32;
        __syncthreads();
        // stage V: 1280 f4 coalesced (10 per thread)
        #pragma unroll
        for (int q = 0; q < 10; q++) {
            int idx = t + q*128;
            *(float4*)&sV[idx*4] =
                *(const float4*)(g_V + (size_t)bs0*CO + (size_t)idx*4);
        }
        // stage x: direct copy, k-contiguous (256 f4)
        #pragma unroll
        for (int q = 0; q < 2; q++) {
            int idx = t + q*128;           // 0..255
            int bb = idx >> 3, kq = idx & 7;
            *(float4*)&sXa[bb*32 + kq*4] =
                *(const float4*)(x + (size_t)(bs0+bb)*KK + k0 + kq*4);
        }
        __syncthreads();

        #pragma unroll 2
        for (int b = 0; b < 32; b++) {
            const float* xr = &sXa[b*32 + wk];
            ulonglong2 xa = *(const ulonglong2*)xr;        // k pairs 0,1
            ulonglong2 xc = *(const ulonglong2*)(xr + 4);  // k pairs 2,3
            ull xp[4] = {xa.x, xa.y, xc.x, xc.y};
            const float* vr = &sV[b*160 + l];
            ull vs[5];
            #pragma unroll
            for (int j = 0; j < 5; j++) vs[j] = splat2(vr[32*j]);
            #pragma unroll
            for (int kp = 0; kp < 4; kp++)
                #pragma unroll
                for (int j = 0; j < 5; j++)
                    acc[kp][j] = ffma2(xp[kp], vs[j], acc[kp][j]);
        }
    }
    __syncthreads();

    // spill partial G: sG[k][co], stride 162, coalesced scalar stores
    #pragma unroll
    for (int kp = 0; kp < 4; kp++) {
        float lo[5], hi[5];
        #pragma unroll
        for (int j = 0; j < 5; j++) unpack2(acc[kp][j], &lo[j], &hi[j]);
        float* ra = &sm[(wk + 2*kp)*162 + l];
        float* rb = ra + 162;
        #pragma unroll
        for (int j = 0; j < 5; j++) { ra[32*j] = lo[j]; rb[32*j] = hi[j]; }
    }
    __syncthreads();

    // contraction: warp w -> route r0+w
    int r = r0 + w;
    const float* G = &sm[(w*8)*162];
    for (int c = 0; c < CC; c++) {
        float4 w4 = *(const float4*)(W + ((size_t)r*CC + c)*OO*II + 4*l);
        int e0 = 4*l;
        float p = w4.x * G[((e0  )&7)*162 + c*16 + ((e0  )>>3)]
                + w4.y * G[((e0+1)&7)*162 + c*16 + ((e0+1)>>3)]
                + w4.z * G[((e0+2)&7)*162 + c*16 + ((e0+2)>>3)]
                + w4.w * G[((e0+3)&7)*162 + c*16 + ((e0+3)>>3)];
        #pragma unroll
        for (int off = 16; off; off >>= 1)
            p += __shfl_xor_sync(0xffffffffu, p, off);
        if (l == 0) atomicAdd(&g_b[c*RR + r], p * (1.0f / (float)BB));
    }
}

// ---------------------------------------------------------------------------
// softmax over routes per class ([c][r] layout)
// ---------------------------------------------------------------------------
__global__ void __launch_bounds__(256) k_softmax() {
    int c = blockIdx.x, t = threadIdx.x;
    __shared__ float red[8];

    float v[5];
    #pragma unroll
    for (int q = 0; q < 5; q++) {
        int r = t + q*256;
        v[q] = (r < RR) ? g_b[c*RR + r] : -1e30f;
    }
    float m = fmaxf(fmaxf(fmaxf(v[0], v[1]), fmaxf(v[2], v[3])), v[4]);
    #pragma unroll
    for (int off = 16; off; off >>= 1) m = fmaxf(m, __shfl_xor_sync(~0u, m, off));
    if ((t & 31) == 0) red[t >> 5] = m;
    __syncthreads();
    m = red[0];
    #pragma unroll
    for (int q = 1; q < 8; q++) m = fmaxf(m, red[q]);

    float e[5], sum = 0.0f;
    #pragma unroll
    for (int q = 0; q < 5; q++) {
        int r = t + q*256;
        e[q] = (r < RR) ? __expf(v[q] - m) : 0.0f;
        sum += e[q];
    }
    #pragma unroll
    for (int off = 16; off; off >>= 1) sum += __shfl_xor_sync(~0u, sum, off);
    __syncthreads();
    if ((t & 31) == 0) red[t >> 5] = sum;
    __syncthreads();
    sum = 0.0f;
    #pragma unroll
    for (int q = 0; q < 8; q++) sum += red[q];
    float inv = 1.0f / sum;

    #pragma unroll
    for (int q = 0; q < 5; q++) {
        int r = t + q*256;
        if (r < RR) g_c[c*RR + r] = e[q] * inv;
    }
}

// ---------------------------------------------------------------------------
extern "C" void kernel_launch(void* const* d_in, const int* in_sizes, int n_in,
                              void* d_out, int out_size) {
    const float* x = (const float*)d_in[0];
    const float* W = (const float*)d_in[1];
    if (in_sizes[0] == RR*CC*OO*II && in_sizes[1] == BB*RR*II) {
        W = (const float*)d_in[0];
        x = (const float*)d_in[1];
    }
    float* out = (float*)d_out;

    for (int it = 0; it < NITER; it++) {
        k_spart<<<dim3(KSPLIT, 8), 128>>>(x, W, it == 0 ? 1 : 0);
        k_sqreduce<<<160, 256>>>(out, it == NITER - 1 ? 1 : 0,
                                 it == 0 ? 1 : 0);
        if (it < NITER - 1) {
            k_agree<<<dim3(288, 4), 128>>>(x, W);
            k_softmax<<<CC, 256>>>();
        }
    }
}

// round 11
// speedup vs baseline: 1.4870x; 1.0332x over previous
#include <cuda_runtime.h>

#define BB 256
#define RR 1152
#define CC 10
#define OO 16
#define II 8
#define CO 160            // CC*OO
#define KK (RR*II)        // 9216
#define NITER 3
#define KSPLIT 72         // k_spart: K chunks of 128 k (16 r)

typedef unsigned long long ull;

__device__ float g_b[CC*RR];             // logits [c][r]
__device__ float g_c[CC*RR];             // couplings [c][r]
__device__ float g_part[KSPLIT*BB*CO];   // split-K partials of S (11.8 MB)
__device__ float g_V[BB*CO];             // squashed v [b][co]

// ---------------- f32x2 helpers --------------------------------------------
__device__ __forceinline__ ull ffma2(ull a, ull b, ull c) {
    ull d;
    asm("fma.rn.f32x2 %0, %1, %2, %3;" : "=l"(d) : "l"(a), "l"(b), "l"(c));
    return d;
}
__device__ __forceinline__ ull splat2(float x) {
    ull d; unsigned u = __float_as_uint(x);
    asm("mov.b64 %0, {%1, %1};" : "=l"(d) : "r"(u));
    return d;
}
__device__ __forceinline__ void unpack2(ull a, float* lo, float* hi) {
    unsigned l_, h_;
    asm("mov.b64 {%0, %1}, %2;" : "=r"(l_), "=r"(h_) : "l"(a));
    *lo = __uint_as_float(l_); *hi = __uint_as_float(h_);
}
__device__ __forceinline__ float squashf(float s) {
    return s * fabsf(s) / (1.0f + s*s);
}

// ---------------------------------------------------------------------------
// s GEMM partials: part[ks][b][co] = sum_{k in 128-chunk} (cW)[k,co]*x[b,k]
// grid (72, 8), 128 thr, ~4 CTAs/SM in ONE wave. Block tile 32b x 160co,
// 16 double-buffered stages of 8 k. Warp w: b rows [w*8, w*8+8), all co.
// Lane l: co {l+32j}. Per k-step: 2 bcast LDS.128 + 5 coalesced LDS.32
// + 5 splat + 20 FFMA2 (all smem ops 1 wavefront).
// ---------------------------------------------------------------------------
__global__ void __launch_bounds__(128, 5) k_spart(const float* __restrict__ x,
                                                  const float* __restrict__ W,
                                                  int uniform) {
    __shared__ __align__(16) float sX[2][8][32];     // [k][b]
    __shared__ __align__(16) float sW[2][8][160];    // [k][co], c-scaled
    __shared__ float sc[160];

    int t = threadIdx.x;
    int w = t >> 5, l = t & 31;
    int ks = blockIdx.x, bt = blockIdx.y;
    int r0 = ks * 16;
    int b0 = bt * 32;
    int wb = w * 8;                   // warp's local b base

    // couplings for the 16 r of this chunk
    if (t < 128)
        sc[t] = uniform ? (1.0f / (float)RR)
                        : g_c[(t % 10)*RR + r0 + (t / 10)];
    if (t < 32)
        sc[t + 128] = uniform ? (1.0f / (float)RR)
                              : g_c[((t + 128) % 10)*RR + r0 + ((t + 128) / 10)];

    // staging roles
    int xb = t >> 1, xh = t & 1;      // t<64: local b, k-half
    float4 rx = make_float4(0,0,0,0);
    float4 rwa, rwb, rwc, rwd;
    float rs1 = 0.0f, rs2 = 0.0f;

    __syncthreads();   // sc ready

    // prologue: load stage 0
    if (t < 64)
        rx = *(const float4*)(x + (size_t)(b0+xb)*KK + r0*8 + xh*4);
    {
        const float* wp = W + ((size_t)r0*CO + t)*II;
        rwa = *(const float4*)wp; rwb = *(const float4*)(wp + 4);
        rs1 = sc[t >> 4];
        if (t < 32) {
            const float* wq = W + ((size_t)r0*CO + t + 128)*II;
            rwc = *(const float4*)wq; rwd = *(const float4*)(wq + 4);
            rs2 = sc[(t + 128) >> 4];
        }
    }
    // commit stage 0
    if (t < 64) {
        sX[0][xh*4+0][xb] = rx.x; sX[0][xh*4+1][xb] = rx.y;
        sX[0][xh*4+2][xb] = rx.z; sX[0][xh*4+3][xb] = rx.w;
    }
    sW[0][0][t] = rwa.x*rs1; sW[0][1][t] = rwa.y*rs1;
    sW[0][2][t] = rwa.z*rs1; sW[0][3][t] = rwa.w*rs1;
    sW[0][4][t] = rwb.x*rs1; sW[0][5][t] = rwb.y*rs1;
    sW[0][6][t] = rwb.z*rs1; sW[0][7][t] = rwb.w*rs1;
    if (t < 32) {
        sW[0][0][t+128] = rwc.x*rs2; sW[0][1][t+128] = rwc.y*rs2;
        sW[0][2][t+128] = rwc.z*rs2; sW[0][3][t+128] = rwc.w*rs2;
        sW[0][4][t+128] = rwd.x*rs2; sW[0][5][t+128] = rwd.y*rs2;
        sW[0][6][t+128] = rwd.z*rs2; sW[0][7][t+128] = rwd.w*rs2;
    }

    ull acc[4][5];
    #pragma unroll
    for (int bp = 0; bp < 4; bp++)
        #pragma unroll
        for (int j = 0; j < 5; j++) acc[bp][j] = 0ull;

    for (int s = 0; s < 16; s++) {
        int p = s & 1;
        if (s < 15) {    // prefetch stage s+1
            int r = r0 + s + 1;
            if (t < 64)
                rx = *(const float4*)(x + (size_t)(b0+xb)*KK + r*8 + xh*4);
            const float* wp = W + ((size_t)r*CO + t)*II;
            rwa = *(const float4*)wp; rwb = *(const float4*)(wp + 4);
            rs1 = sc[(s+1)*10 + (t >> 4)];
            if (t < 32) {
                const float* wq = W + ((size_t)r*CO + t + 128)*II;
                rwc = *(const float4*)wq; rwd = *(const float4*)(wq + 4);
                rs2 = sc[(s+1)*10 + ((t + 128) >> 4)];
            }
        }
        __syncthreads();   // stage s visible

        #pragma unroll
        for (int kk = 0; kk < 8; kk++) {
            const float* xr = &sX[p][kk][wb];
            ulonglong2 xa = *(const ulonglong2*)xr;         // b pairs 0,1
            ulonglong2 xc = *(const ulonglong2*)(xr + 4);   // b pairs 2,3
            ull xp[4] = {xa.x, xa.y, xc.x, xc.y};
            const float* wr = &sW[p][kk][l];
            ull ws[5];
            #pragma unroll
            for (int j = 0; j < 5; j++) ws[j] = splat2(wr[32*j]);
            #pragma unroll
            for (int bp = 0; bp < 4; bp++)
                #pragma unroll
                for (int j = 0; j < 5; j++)
                    acc[bp][j] = ffma2(xp[bp], ws[j], acc[bp][j]);
        }

        if (s < 15) {    // commit prefetched stage into the other buffer
            int q = (s + 1) & 1;
            if (t < 64) {
                sX[q][xh*4+0][xb] = rx.x; sX[q][xh*4+1][xb] = rx.y;
                sX[q][xh*4+2][xb] = rx.z; sX[q][xh*4+3][xb] = rx.w;
            }
            sW[q][0][t] = rwa.x*rs1; sW[q][1][t] = rwa.y*rs1;
            sW[q][2][t] = rwa.z*rs1; sW[q][3][t] = rwa.w*rs1;
            sW[q][4][t] = rwb.x*rs1; sW[q][5][t] = rwb.y*rs1;
            sW[q][6][t] = rwb.z*rs1; sW[q][7][t] = rwb.w*rs1;
            if (t < 32) {
                sW[q][0][t+128] = rwc.x*rs2; sW[q][1][t+128] = rwc.y*rs2;
                sW[q][2][t+128] = rwc.z*rs2; sW[q][3][t+128] = rwc.w*rs2;
                sW[q][4][t+128] = rwd.x*rs2; sW[q][5][t+128] = rwd.y*rs2;
                sW[q][6][t+128] = rwd.z*rs2; sW[q][7][t+128] = rwd.w*rs2;
            }
        }
    }

    // epilogue: coalesced scalar stores (lanes = consecutive co)
    float* dst = g_part + (size_t)ks*BB*CO + (size_t)b0*CO;
    #pragma unroll
    for (int bp = 0; bp < 4; bp++) {
        float lo[5], hi[5];
        #pragma unroll
        for (int j = 0; j < 5; j++) unpack2(acc[bp][j], &lo[j], &hi[j]);
        float* ra = dst + (size_t)(wb + 2*bp)*CO + l;
        float* rb = ra + CO;
        #pragma unroll
        for (int j = 0; j < 5; j++) { ra[32*j] = lo[j]; rb[32*j] = hi[j]; }
    }
}

// ---------------------------------------------------------------------------
// reduce split-K partials, squash -> g_V (+ final output); optionally zero g_b
// grid 160 x 256: 64 f4 per block, 4-way p-split (18 each) + smem tree
// ---------------------------------------------------------------------------
__global__ void __launch_bounds__(256) k_sqreduce(float* __restrict__ out,
                                                  int write_out, int zero_b) {
    __shared__ float4 red[256];
    int t = threadIdx.x;
    if (zero_b) {
        int gid = blockIdx.x * 256 + t;
        if (gid < CC*RR) g_b[gid] = 0.0f;
    }
    int i4 = t & 63, pg = t >> 6;
    int idx4 = blockIdx.x * 64 + i4;
    float4 s = make_float4(0,0,0,0);
    #pragma unroll 6
    for (int p = pg*18; p < (pg+1)*18; p++) {
        float4 v = *(const float4*)(g_part + (size_t)p*BB*CO + (size_t)idx4*4);
        s.x += v.x; s.y += v.y; s.z += v.z; s.w += v.w;
    }
    red[t] = s;
    __syncthreads();
    if (t < 64) {
        float4 a = red[t], b = red[t+64], c = red[t+128], d = red[t+192];
        s.x = (a.x + b.x) + (c.x + d.x);
        s.y = (a.y + b.y) + (c.y + d.y);
        s.z = (a.z + b.z) + (c.z + d.z);
        s.w = (a.w + b.w) + (c.w + d.w);
        float4 q;
        q.x = squashf(s.x); q.y = squashf(s.y);
        q.z = squashf(s.z); q.w = squashf(s.w);
        *(float4*)(g_V + (size_t)idx4*4) = q;
        if (write_out) *(float4*)(out + (size_t)idx4*4) = q;
    }
}

// ---------------------------------------------------------------------------
// agree: partial G[k,co] = sum_{b quarter} x[b,k]*V[b,co]; contract with W,
// atomicAdd logits. grid (288, 4), 128 thr, 4 routes (32 k) per CTA.
// ---------------------------------------------------------------------------
__global__ void __launch_bounds__(128, 5) k_agree(const float* __restrict__ x,
                                                  const float* __restrict__ W) {
    __shared__ __align__(16) float sm[6272];   // reused as sG [32][162]
    float* sV  = sm;          // [32][160] = 5120
    float* sXa = sm + 5120;   // [32][32]  = 1024

    int t = threadIdx.x;
    int w = t >> 5, l = t & 31;
    int r0 = blockIdx.x * 4;       // 4 routes
    int k0 = r0 * 8;               // 32 k
    int wk = w * 8;                // warp's local k base

    ull acc[4][5];                 // 4 k-pairs x 5 strided co
    #pragma unroll
    for (int kp = 0; kp < 4; kp++)
        #pragma unroll
        for (int j = 0; j < 5; j++) acc[kp][j] = 0ull;

    for (int sub = 0; sub < 2; sub++) {
        int bs0 = blockIdx.y * 64 + sub * 32;
        __syncthreads();
        // stage V: 1280 f4 coalesced (10 per thread)
        #pragma unroll
        for (int q = 0; q < 10; q++) {
            int idx = t + q*128;
            *(float4*)&sV[idx*4] =
                *(const float4*)(g_V + (size_t)bs0*CO + (size_t)idx*4);
        }
        // stage x: direct copy, k-contiguous (256 f4)
        #pragma unroll
        for (int q = 0; q < 2; q++) {
            int idx = t + q*128;           // 0..255
            int bb = idx >> 3, kq = idx & 7;
            *(float4*)&sXa[bb*32 + kq*4] =
                *(const float4*)(x + (size_t)(bs0+bb)*KK + k0 + kq*4);
        }
        __syncthreads();

        #pragma unroll 2
        for (int b = 0; b < 32; b++) {
            const float* xr = &sXa[b*32 + wk];
            ulonglong2 xa = *(const ulonglong2*)xr;        // k pairs 0,1
            ulonglong2 xc = *(const ulonglong2*)(xr + 4);  // k pairs 2,3
            ull xp[4] = {xa.x, xa.y, xc.x, xc.y};
            const float* vr = &sV[b*160 + l];
            ull vs[5];
            #pragma unroll
            for (int j = 0; j < 5; j++) vs[j] = splat2(vr[32*j]);
            #pragma unroll
            for (int kp = 0; kp < 4; kp++)
                #pragma unroll
                for (int j = 0; j < 5; j++)
                    acc[kp][j] = ffma2(xp[kp], vs[j], acc[kp][j]);
        }
    }
    __syncthreads();

    // spill partial G: sG[k][co], stride 162, coalesced scalar stores
    #pragma unroll
    for (int kp = 0; kp < 4; kp++) {
        float lo[5], hi[5];
        #pragma unroll
        for (int j = 0; j < 5; j++) unpack2(acc[kp][j], &lo[j], &hi[j]);
        float* ra = &sm[(wk + 2*kp)*162 + l];
        float* rb = ra + 162;
        #pragma unroll
        for (int j = 0; j < 5; j++) { ra[32*j] = lo[j]; rb[32*j] = hi[j]; }
    }
    __syncthreads();

    // contraction: warp w -> route r0+w
    int r = r0 + w;
    const float* G = &sm[(w*8)*162];
    for (int c = 0; c < CC; c++) {
        float4 w4 = *(const float4*)(W + ((size_t)r*CC + c)*OO*II + 4*l);
        int e0 = 4*l;
        float p = w4.x * G[((e0  )&7)*162 + c*16 + ((e0  )>>3)]
                + w4.y * G[((e0+1)&7)*162 + c*16 + ((e0+1)>>3)]
                + w4.z * G[((e0+2)&7)*162 + c*16 + ((e0+2)>>3)]
                + w4.w * G[((e0+3)&7)*162 + c*16 + ((e0+3)>>3)];
        #pragma unroll
        for (int off = 16; off; off >>= 1)
            p += __shfl_xor_sync(0xffffffffu, p, off);
        if (l == 0) atomicAdd(&g_b[c*RR + r], p * (1.0f / (float)BB));
    }
}

// ---------------------------------------------------------------------------
// softmax over routes per class ([c][r] layout)
// ---------------------------------------------------------------------------
__global__ void __launch_bounds__(256) k_softmax() {
    int c = blockIdx.x, t = threadIdx.x;
    __shared__ float red[8];

    float v[5];
    #pragma unroll
    for (int q = 0; q < 5; q++) {
        int r = t + q*256;
        v[q] = (r < RR) ? g_b[c*RR + r] : -1e30f;
    }
    float m = fmaxf(fmaxf(fmaxf(v[0], v[1]), fmaxf(v[2], v[3])), v[4]);
    #pragma unroll
    for (int off = 16; off; off >>= 1) m = fmaxf(m, __shfl_xor_sync(~0u, m, off));
    if ((t & 31) == 0) red[t >> 5] = m;
    __syncthreads();
    m = red[0];
    #pragma unroll
    for (int q = 1; q < 8; q++) m = fmaxf(m, red[q]);

    float e[5], sum = 0.0f;
    #pragma unroll
    for (int q = 0; q < 5; q++) {
        int r = t + q*256;
        e[q] = (r < RR) ? __expf(v[q] - m) : 0.0f;
        sum += e[q];
    }
    #pragma unroll
    for (int off = 16; off; off >>= 1) sum += __shfl_xor_sync(~0u, sum, off);
    __syncthreads();
    if ((t & 31) == 0) red[t >> 5] = sum;
    __syncthreads();
    sum = 0.0f;
    #pragma unroll
    for (int q = 0; q < 8; q++) sum += red[q];
    float inv = 1.0f / sum;

    #pragma unroll
    for (int q = 0; q < 5; q++) {
        int r = t + q*256;
        if (r < RR) g_c[c*RR + r] = e[q] * inv;
    }
}

// ---------------------------------------------------------------------------
extern "C" void kernel_launch(void* const* d_in, const int* in_sizes, int n_in,
                              void* d_out, int out_size) {
    const float* x = (const float*)d_in[0];
    const float* W = (const float*)d_in[1];
    if (in_sizes[0] == RR*CC*OO*II && in_sizes[1] == BB*RR*II) {
        W = (const float*)d_in[0];
        x = (const float*)d_in[1];
    }
    float* out = (float*)d_out;

    for (int it = 0; it < NITER; it++) {
        k_spart<<<dim3(KSPLIT, 8), 128>>>(x, W, it == 0 ? 1 : 0);
        k_sqreduce<<<160, 256>>>(out, it == NITER - 1 ? 1 : 0,
                                 it == 0 ? 1 : 0);
        if (it < NITER - 1) {
            k_agree<<<dim3(288, 4), 128>>>(x, W);
            k_softmax<<<CC, 256>>>();
        }
    }
}